// round 10
// baseline (speedup 1.0000x reference)
#include <cuda_runtime.h>
#include <cstdint>

// DeltaLoss, rank-96 factorization. R10: occupancy fix for lse_main.
//  prep : blocks 0..191 -> Gti rows; blocks 192..767 -> warp-per-pair meta + zeroing.
//  lse  : PBLK=256 x QBLK=128 tiles, grid 648 (~4 CTAs/SM), capped unroll,
//         packed (k1,base) float2, ticket finalize.
// SHIFT=30 fixed-shift LSE: x<=100 -> no overflow; sums stay normal fp32.

#define NN    96
#define D     512
#define P2    4560            // NN*(NN-1)/2
#define P2PAD 4608
#define PBLK  256
#define QBLK  128
#define GQ    (P2PAD / QBLK)  // 36
#define GP    (P2PAD / PBLK)  // 18
#define NBLOCKS (GQ * GP)     // 648
#define NGRAMB 192
#define NMETAB 576
#define K2C   (-43.28085122666891f)   // -30*log2(e)
#define L2E100 144.26950408889634f    // 100*log2(e)

// ---- scratch ----
__device__ float g_gti[NN * NN];
__device__ uint32_t g_ij[P2PAD];
__device__ float g_k1[P2PAD];
__device__ float g_si[P2PAD];
__device__ float g_diag[P2PAD];
__device__ float g_rowSum[P2PAD];
__device__ float g_colSum[P2PAD];
__device__ unsigned int g_done;

__device__ __forceinline__ float ex2f(float x) {
    float y;
    asm("ex2.approx.f32 %0, %1;" : "=f"(y) : "f"(x));
    return y;
}
__device__ __forceinline__ uint32_t smem_u32(const void* p) {
    uint32_t a;
    asm("{ .reg .u64 t; cvta.to.shared.u64 t, %1; cvt.u32.u64 %0, t; }" : "=r"(a) : "l"(p));
    return a;
}
__device__ __forceinline__ float warp_sum(float v) {
    #pragma unroll
    for (int o = 16; o > 0; o >>= 1) v += __shfl_xor_sync(0xffffffffu, v, o);
    return v;
}

// ---- prep: Gti (192 blocks) + per-pair meta & zeroing (576 blocks) ----
__global__ __launch_bounds__(256) void prep_kernel(const float* __restrict__ txtf,
                                                   const float* __restrict__ imgf) {
    __shared__ float srow[D];
    const int bid = blockIdx.x;
    const int tid = threadIdx.x;
    const int w = tid >> 5, lane = tid & 31;

    if (bid < NGRAMB) {
        const int b = bid >> 1, half = bid & 1;
        if (tid < 128) ((float4*)srow)[tid] = ((const float4*)(txtf + b * D))[tid];
        __syncthreads();
        #pragma unroll
        for (int k = 0; k < 6; ++k) {
            const int r = half * 48 + w * 6 + k;
            const float4* __restrict__ vec = (const float4*)(imgf + r * D);
            float s0 = 0.f, s1 = 0.f;
            #pragma unroll
            for (int e = 0; e < 4; e += 2) {
                const float4 a0 = ((const float4*)srow)[lane + e * 32];
                const float4 g0 = vec[lane + e * 32];
                const float4 a1 = ((const float4*)srow)[lane + (e + 1) * 32];
                const float4 g1 = vec[lane + (e + 1) * 32];
                s0 = fmaf(a0.x, g0.x, s0); s0 = fmaf(a0.y, g0.y, s0);
                s0 = fmaf(a0.z, g0.z, s0); s0 = fmaf(a0.w, g0.w, s0);
                s1 = fmaf(a1.x, g1.x, s1); s1 = fmaf(a1.y, g1.y, s1);
                s1 = fmaf(a1.z, g1.z, s1); s1 = fmaf(a1.w, g1.w, s1);
            }
            const float s = warp_sum(s0 + s1);
            if (lane == 0) g_gti[b * NN + r] = s;
        }
        return;
    }

    const int m = bid - NGRAMB;
    if (tid < 8)              g_rowSum[m * 8 + tid] = 0.f;
    else if (tid < 16)        g_colSum[m * 8 + tid - 8] = 0.f;
    else if (tid == 16 && m == 0) g_done = 0u;

    const int p = m * 8 + w;
    if (p >= P2) {
        if (p < P2PAD && lane == 0) {
            g_ij[p] = 0u; g_k1[p] = 0.f; g_si[p] = 0.f; g_diag[p] = 0.f;
        }
        return;
    }

    const float disc = (2.f * NN - 1.f) * (2.f * NN - 1.f) - 8.f * (float)p;
    int i = (int)(((2.f * NN - 1.f) - sqrtf(disc)) * 0.5f);
    i = i < 0 ? 0 : (i > NN - 2 ? NN - 2 : i);
    while (i > 0 && p < i * (191 - i) / 2) --i;
    while (p >= (i + 1) * (190 - i) / 2) ++i;
    const int j = i + 1 + (p - i * (191 - i) / 2);

    const float4* __restrict__ ti = (const float4*)(txtf + i * D);
    const float4* __restrict__ tj = (const float4*)(txtf + j * D);
    const float4* __restrict__ ui = (const float4*)(imgf + i * D);
    const float4* __restrict__ uj = (const float4*)(imgf + j * D);
    float ntt = 0.f, nii = 0.f, dd = 0.f;
    #pragma unroll
    for (int e = 0; e < 4; ++e) {
        const float4 a = ti[lane + e * 32], b4 = tj[lane + e * 32];
        const float4 c = ui[lane + e * 32], d4 = uj[lane + e * 32];
        const float t0 = a.x - b4.x, t1 = a.y - b4.y, t2 = a.z - b4.z, t3 = a.w - b4.w;
        const float u0 = c.x - d4.x, u1 = c.y - d4.y, u2 = c.z - d4.z, u3 = c.w - d4.w;
        ntt = fmaf(t0, t0, ntt); ntt = fmaf(t1, t1, ntt);
        ntt = fmaf(t2, t2, ntt); ntt = fmaf(t3, t3, ntt);
        nii = fmaf(u0, u0, nii); nii = fmaf(u1, u1, nii);
        nii = fmaf(u2, u2, nii); nii = fmaf(u3, u3, nii);
        dd  = fmaf(t0, u0, dd);  dd  = fmaf(t1, u1, dd);
        dd  = fmaf(t2, u2, dd);  dd  = fmaf(t3, u3, dd);
    }
    ntt = warp_sum(ntt); nii = warp_sum(nii); dd = warp_sum(dd);
    if (lane == 0) {
        const float st = 1.f / (sqrtf(ntt) + 1e-8f);
        const float si = 1.f / (sqrtf(nii) + 1e-8f);
        g_ij[p] = (uint32_t)i | ((uint32_t)j << 8);
        g_k1[p] = L2E100 * st;
        g_si[p] = si;
        g_diag[p] = 100.f * st * si * dd;
    }
}

// ---- main: W tile in smem, 256p x 128q per block, fused LSE, ticket finalize ----
__global__ void __launch_bounds__(256, 4) lse_main(float* __restrict__ out) {
    extern __shared__ float sm[];
    float* Wsm = sm;                                   // [96][QBLK]
    float2* ksm = (float2*)(sm + NN * QBLK);           // [PBLK] (k1, base)
    uint32_t* offsm = (uint32_t*)(ksm + PBLK);         // [PBLK] packed byte offsets
    float* red = (float*)(offsm + PBLK);               // [8]

    const int tid = threadIdx.x;
    const int q0 = blockIdx.x * QBLK;
    const int p0 = blockIdx.y * PBLK;

    // --- build W tile: Wsm[r][q] = si_q * (Gti[r][i_q] - Gti[r][j_q]) ---
    {
        const int q = tid & 127;
        const int half = tid >> 7;                     // r in [half*48, half*48+48)
        const uint32_t ij = g_ij[q0 + q];
        const float si = g_si[q0 + q];
        const int iq = (int)(ij & 255u), jq = (int)(ij >> 8);
        const float* __restrict__ gi = g_gti + half * 48 * NN;
        #pragma unroll 8
        for (int k = 0; k < 48; ++k) {
            const float a = __ldg(gi + k * NN + iq);
            const float b = __ldg(gi + k * NN + jq);
            Wsm[(half * 48 + k) * QBLK + q] = si * (a - b);
        }
        const int p = p0 + tid;
        ksm[tid] = make_float2(g_k1[p], (p < P2) ? K2C : -2000.f);
        const uint32_t pij = g_ij[p];
        offsm[tid] = ((pij & 255u) * (QBLK * 4)) | (((pij >> 8) * (QBLK * 4)) << 16);
    }
    __syncthreads();

    const int w = tid >> 5, lane = tid & 31;
    const uint32_t wbase = smem_u32(Wsm) + (uint32_t)lane * 16u;
    const int pbase = w * 32;                          // 32 p per warp
    float c0 = 0.f, c1 = 0.f, c2 = 0.f, c3 = 0.f;

    const int gq = q0 + 4 * lane;
    const bool fullq = (q0 + QBLK <= P2);
    const float mq0 = (fullq || gq + 0 < P2) ? 1.f : 0.f;
    const float mq1 = (fullq || gq + 1 < P2) ? 1.f : 0.f;
    const float mq2 = (fullq || gq + 2 < P2) ? 1.f : 0.f;
    const float mq3 = (fullq || gq + 3 < P2) ? 1.f : 0.f;

    #pragma unroll 1
    for (int g = 0; g < 8; ++g) {                      // 8 groups of 4 p
        float rsv[4];
        #pragma unroll
        for (int u = 0; u < 4; ++u) {
            const int p = pbase + g * 4 + u;
            const uint32_t off = offsm[p];
            const float2 kb = ksm[p];
            float4 vi, vj;
            asm volatile("ld.shared.v4.f32 {%0,%1,%2,%3}, [%4];"
                : "=f"(vi.x), "=f"(vi.y), "=f"(vi.z), "=f"(vi.w)
                : "r"(wbase + (off & 0xFFFFu)));
            asm volatile("ld.shared.v4.f32 {%0,%1,%2,%3}, [%4];"
                : "=f"(vj.x), "=f"(vj.y), "=f"(vj.z), "=f"(vj.w)
                : "r"(wbase + (off >> 16)));
            const float d0 = vi.x - vj.x, d1 = vi.y - vj.y;
            const float d2 = vi.z - vj.z, d3 = vi.w - vj.w;
            const float e0 = ex2f(fmaf(d0, kb.x, kb.y)) + ex2f(fmaf(d0, -kb.x, kb.y));
            const float e1 = ex2f(fmaf(d1, kb.x, kb.y)) + ex2f(fmaf(d1, -kb.x, kb.y));
            const float e2 = ex2f(fmaf(d2, kb.x, kb.y)) + ex2f(fmaf(d2, -kb.x, kb.y));
            const float e3 = ex2f(fmaf(d3, kb.x, kb.y)) + ex2f(fmaf(d3, -kb.x, kb.y));
            c0 += e0; c1 += e1; c2 += e2; c3 += e3;
            if (fullq) {
                rsv[u] = (e0 + e1) + (e2 + e3);
            } else {
                float rs = e0 * mq0;
                rs = fmaf(e1, mq1, rs);
                rs = fmaf(e2, mq2, rs);
                rs = fmaf(e3, mq3, rs);
                rsv[u] = rs;
            }
        }
        // merged 4-way butterfly: lane-group (bit4, bit3) holds row sum of
        // p = pbase + g*4 + idx, idx = bit4 | (bit3 << 1)
        float v0 = rsv[0] + __shfl_xor_sync(0xffffffffu, rsv[0], 16);
        float t1 = rsv[1] + __shfl_xor_sync(0xffffffffu, rsv[1], 16);
        v0 = (lane & 16) ? t1 : v0;
        float v1 = rsv[2] + __shfl_xor_sync(0xffffffffu, rsv[2], 16);
        float t3 = rsv[3] + __shfl_xor_sync(0xffffffffu, rsv[3], 16);
        v1 = (lane & 16) ? t3 : v1;
        float u0 = v0 + __shfl_xor_sync(0xffffffffu, v0, 8);
        float u1 = v1 + __shfl_xor_sync(0xffffffffu, v1, 8);
        u0 = (lane & 8) ? u1 : u0;
        u0 += __shfl_xor_sync(0xffffffffu, u0, 4);
        u0 += __shfl_xor_sync(0xffffffffu, u0, 2);
        u0 += __shfl_xor_sync(0xffffffffu, u0, 1);
        if ((lane & 7) == 0) {
            const int idx = ((lane >> 4) & 1) | ((lane >> 2) & 2);
            atomicAdd(&g_rowSum[p0 + pbase + g * 4 + idx], u0);
        }
    }

    atomicAdd(&g_colSum[gq + 0], c0);
    atomicAdd(&g_colSum[gq + 1], c1);
    atomicAdd(&g_colSum[gq + 2], c2);
    atomicAdd(&g_colSum[gq + 3], c3);

    // --- last-block finalize (ticket) ---
    __syncthreads();
    __shared__ unsigned int s_last;
    if (tid == 0) {
        __threadfence();
        s_last = (atomicAdd(&g_done, 1u) == (unsigned)(NBLOCKS - 1)) ? 1u : 0u;
    }
    __syncthreads();
    if (s_last) {
        __threadfence();
        float s = 0.f;
        for (int p = tid; p < P2; p += 256)
            s += 30.0f + 0.5f * (logf(g_rowSum[p]) + logf(g_colSum[p])) - g_diag[p];
        s = warp_sum(s);
        if ((tid & 31) == 0) red[tid >> 5] = s;
        __syncthreads();
        if (tid == 0) {
            float tot = 0.f;
            #pragma unroll
            for (int k = 0; k < 8; ++k) tot += red[k];
            out[0] = tot / (float)P2;
        }
    }
}

extern "C" void kernel_launch(void* const* d_in, const int* in_sizes, int n_in,
                              void* d_out, int out_size) {
    const float* txtf = (const float*)d_in[0];
    const float* imgf = (const float*)d_in[1];
    (void)in_sizes; (void)n_in; (void)out_size;
    float* out = (float*)d_out;

    const int smem = (NN * QBLK) * 4 + PBLK * 8 + PBLK * 4 + 32;   // 52256 B
    static int configured = 0;
    if (!configured) {
        cudaFuncSetAttribute(lse_main, cudaFuncAttributeMaxDynamicSharedMemorySize, smem);
        configured = 1;
    }

    prep_kernel<<<NGRAMB + NMETAB, 256>>>(txtf, imgf);
    lse_main<<<dim3(GQ, GP), 256, smem>>>(out);
}

// round 11
// speedup vs baseline: 1.1718x; 1.1718x over previous
#include <cuda_runtime.h>
#include <cstdint>

// DeltaLoss, rank-96 factorization. R11: QBLK=64 -> 24KB W tile -> 6 CTAs/SM
// (48 warps) so the LDS(29cyc)+MUFU(16cyc) chain is latency-hidden.
//  prep : blocks 0..191 -> Gti rows; blocks 192..767 -> warp-per-pair meta + zeroing.
//  lse  : PBLK=256 x QBLK=64 tiles, grid 1296, lanes own a q-pair (LDS.64),
//         merged-butterfly row reduce, ticket finalize.
// SHIFT=30 fixed-shift LSE: x<=100 -> no overflow; sums stay normal fp32.

#define NN    96
#define D     512
#define P2    4560            // NN*(NN-1)/2
#define P2PAD 4608
#define PBLK  256
#define QBLK  64
#define GQ    (P2PAD / QBLK)  // 72
#define GP    (P2PAD / PBLK)  // 18
#define NBLOCKS (GQ * GP)     // 1296
#define NGRAMB 192
#define NMETAB 576
#define K2C   (-43.28085122666891f)   // -30*log2(e)
#define L2E100 144.26950408889634f    // 100*log2(e)

// ---- scratch ----
__device__ float g_gti[NN * NN];
__device__ uint32_t g_ij[P2PAD];
__device__ float g_k1[P2PAD];
__device__ float g_si[P2PAD];
__device__ float g_diag[P2PAD];
__device__ float g_rowSum[P2PAD];
__device__ float g_colSum[P2PAD];
__device__ unsigned int g_done;

__device__ __forceinline__ float ex2f(float x) {
    float y;
    asm("ex2.approx.f32 %0, %1;" : "=f"(y) : "f"(x));
    return y;
}
__device__ __forceinline__ uint32_t smem_u32(const void* p) {
    uint32_t a;
    asm("{ .reg .u64 t; cvta.to.shared.u64 t, %1; cvt.u32.u64 %0, t; }" : "=r"(a) : "l"(p));
    return a;
}
__device__ __forceinline__ float warp_sum(float v) {
    #pragma unroll
    for (int o = 16; o > 0; o >>= 1) v += __shfl_xor_sync(0xffffffffu, v, o);
    return v;
}

// ---- prep: Gti (192 blocks) + per-pair meta & zeroing (576 blocks) ----
__global__ __launch_bounds__(256) void prep_kernel(const float* __restrict__ txtf,
                                                   const float* __restrict__ imgf) {
    __shared__ float srow[D];
    const int bid = blockIdx.x;
    const int tid = threadIdx.x;
    const int w = tid >> 5, lane = tid & 31;

    if (bid < NGRAMB) {
        const int b = bid >> 1, half = bid & 1;
        if (tid < 128) ((float4*)srow)[tid] = ((const float4*)(txtf + b * D))[tid];
        __syncthreads();
        #pragma unroll
        for (int k = 0; k < 6; ++k) {
            const int r = half * 48 + w * 6 + k;
            const float4* __restrict__ vec = (const float4*)(imgf + r * D);
            float s0 = 0.f, s1 = 0.f;
            #pragma unroll
            for (int e = 0; e < 4; e += 2) {
                const float4 a0 = ((const float4*)srow)[lane + e * 32];
                const float4 g0 = vec[lane + e * 32];
                const float4 a1 = ((const float4*)srow)[lane + (e + 1) * 32];
                const float4 g1 = vec[lane + (e + 1) * 32];
                s0 = fmaf(a0.x, g0.x, s0); s0 = fmaf(a0.y, g0.y, s0);
                s0 = fmaf(a0.z, g0.z, s0); s0 = fmaf(a0.w, g0.w, s0);
                s1 = fmaf(a1.x, g1.x, s1); s1 = fmaf(a1.y, g1.y, s1);
                s1 = fmaf(a1.z, g1.z, s1); s1 = fmaf(a1.w, g1.w, s1);
            }
            const float s = warp_sum(s0 + s1);
            if (lane == 0) g_gti[b * NN + r] = s;
        }
        return;
    }

    const int m = bid - NGRAMB;
    if (tid < 8)              g_rowSum[m * 8 + tid] = 0.f;
    else if (tid < 16)        g_colSum[m * 8 + tid - 8] = 0.f;
    else if (tid == 16 && m == 0) g_done = 0u;

    const int p = m * 8 + w;
    if (p >= P2) {
        if (p < P2PAD && lane == 0) {
            g_ij[p] = 0u; g_k1[p] = 0.f; g_si[p] = 0.f; g_diag[p] = 0.f;
        }
        return;
    }

    const float disc = (2.f * NN - 1.f) * (2.f * NN - 1.f) - 8.f * (float)p;
    int i = (int)(((2.f * NN - 1.f) - sqrtf(disc)) * 0.5f);
    i = i < 0 ? 0 : (i > NN - 2 ? NN - 2 : i);
    while (i > 0 && p < i * (191 - i) / 2) --i;
    while (p >= (i + 1) * (190 - i) / 2) ++i;
    const int j = i + 1 + (p - i * (191 - i) / 2);

    const float4* __restrict__ ti = (const float4*)(txtf + i * D);
    const float4* __restrict__ tj = (const float4*)(txtf + j * D);
    const float4* __restrict__ ui = (const float4*)(imgf + i * D);
    const float4* __restrict__ uj = (const float4*)(imgf + j * D);
    float ntt = 0.f, nii = 0.f, dd = 0.f;
    #pragma unroll
    for (int e = 0; e < 4; ++e) {
        const float4 a = ti[lane + e * 32], b4 = tj[lane + e * 32];
        const float4 c = ui[lane + e * 32], d4 = uj[lane + e * 32];
        const float t0 = a.x - b4.x, t1 = a.y - b4.y, t2 = a.z - b4.z, t3 = a.w - b4.w;
        const float u0 = c.x - d4.x, u1 = c.y - d4.y, u2 = c.z - d4.z, u3 = c.w - d4.w;
        ntt = fmaf(t0, t0, ntt); ntt = fmaf(t1, t1, ntt);
        ntt = fmaf(t2, t2, ntt); ntt = fmaf(t3, t3, ntt);
        nii = fmaf(u0, u0, nii); nii = fmaf(u1, u1, nii);
        nii = fmaf(u2, u2, nii); nii = fmaf(u3, u3, nii);
        dd  = fmaf(t0, u0, dd);  dd  = fmaf(t1, u1, dd);
        dd  = fmaf(t2, u2, dd);  dd  = fmaf(t3, u3, dd);
    }
    ntt = warp_sum(ntt); nii = warp_sum(nii); dd = warp_sum(dd);
    if (lane == 0) {
        const float st = 1.f / (sqrtf(ntt) + 1e-8f);
        const float si = 1.f / (sqrtf(nii) + 1e-8f);
        g_ij[p] = (uint32_t)i | ((uint32_t)j << 8);
        g_k1[p] = L2E100 * st;
        g_si[p] = si;
        g_diag[p] = 100.f * st * si * dd;
    }
}

// ---- main: 24KB W tile, 256p x 64q per block, fused LSE, ticket finalize ----
__global__ void __launch_bounds__(256, 6) lse_main(float* __restrict__ out) {
    __shared__ float Wsm[NN * QBLK];                   // 24576 B
    __shared__ float2 ksm[PBLK];                       // (k1, base)
    __shared__ uint32_t offsm[PBLK];                   // packed byte offsets
    __shared__ float red[8];
    __shared__ unsigned int s_last;

    const int tid = threadIdx.x;
    const int q0 = blockIdx.x * QBLK;
    const int p0 = blockIdx.y * PBLK;

    // --- build W tile: Wsm[r][q] = si_q * (Gti[r][i_q] - Gti[r][j_q]) ---
    {
        const int q = tid & 63;
        const int rg = tid >> 6;                       // 4 groups of 24 rows
        const uint32_t ij = g_ij[q0 + q];
        const float si = g_si[q0 + q];
        const int iq = (int)(ij & 255u), jq = (int)(ij >> 8);
        const float* __restrict__ gi = g_gti + rg * 24 * NN;
        #pragma unroll 8
        for (int k = 0; k < 24; ++k) {
            const float a = __ldg(gi + k * NN + iq);
            const float b = __ldg(gi + k * NN + jq);
            Wsm[(rg * 24 + k) * QBLK + q] = si * (a - b);
        }
        const int p = p0 + tid;
        ksm[tid] = make_float2(g_k1[p], (p < P2) ? K2C : -2000.f);
        const uint32_t pij = g_ij[p];
        offsm[tid] = ((pij & 255u) * (QBLK * 4)) | (((pij >> 8) * (QBLK * 4)) << 16);
    }
    __syncthreads();

    const int w = tid >> 5, lane = tid & 31;
    const uint32_t wbase = smem_u32(Wsm) + (uint32_t)lane * 8u;
    const int pbase = w * 32;                          // 32 p per warp
    float c0 = 0.f, c1 = 0.f;

    const int gq = q0 + 2 * lane;
    const bool fullq = (q0 + QBLK <= P2);
    const float mq0 = (fullq || gq + 0 < P2) ? 1.f : 0.f;
    const float mq1 = (fullq || gq + 1 < P2) ? 1.f : 0.f;

    #pragma unroll 2
    for (int g = 0; g < 8; ++g) {                      // 8 groups of 4 p
        float rsv[4];
        #pragma unroll
        for (int u = 0; u < 4; ++u) {
            const int p = pbase + g * 4 + u;
            const uint32_t off = offsm[p];
            const float2 kb = ksm[p];
            float2 vi, vj;
            asm volatile("ld.shared.v2.f32 {%0,%1}, [%2];"
                : "=f"(vi.x), "=f"(vi.y) : "r"(wbase + (off & 0xFFFFu)));
            asm volatile("ld.shared.v2.f32 {%0,%1}, [%2];"
                : "=f"(vj.x), "=f"(vj.y) : "r"(wbase + (off >> 16)));
            const float d0 = vi.x - vj.x, d1 = vi.y - vj.y;
            const float e0 = ex2f(fmaf(d0, kb.x, kb.y)) + ex2f(fmaf(d0, -kb.x, kb.y));
            const float e1 = ex2f(fmaf(d1, kb.x, kb.y)) + ex2f(fmaf(d1, -kb.x, kb.y));
            c0 += e0; c1 += e1;
            rsv[u] = fullq ? (e0 + e1) : fmaf(e1, mq1, e0 * mq0);
        }
        // merged 4-way butterfly: lane-group (bit4, bit3) holds row sum of
        // p = pbase + g*4 + idx, idx = bit4 | (bit3 << 1)
        float v0 = rsv[0] + __shfl_xor_sync(0xffffffffu, rsv[0], 16);
        float t1 = rsv[1] + __shfl_xor_sync(0xffffffffu, rsv[1], 16);
        v0 = (lane & 16) ? t1 : v0;
        float v1 = rsv[2] + __shfl_xor_sync(0xffffffffu, rsv[2], 16);
        float t3 = rsv[3] + __shfl_xor_sync(0xffffffffu, rsv[3], 16);
        v1 = (lane & 16) ? t3 : v1;
        float u0 = v0 + __shfl_xor_sync(0xffffffffu, v0, 8);
        float u1 = v1 + __shfl_xor_sync(0xffffffffu, v1, 8);
        u0 = (lane & 8) ? u1 : u0;
        u0 += __shfl_xor_sync(0xffffffffu, u0, 4);
        u0 += __shfl_xor_sync(0xffffffffu, u0, 2);
        u0 += __shfl_xor_sync(0xffffffffu, u0, 1);
        if ((lane & 7) == 0) {
            const int idx = ((lane >> 4) & 1) | ((lane >> 2) & 2);
            atomicAdd(&g_rowSum[p0 + pbase + g * 4 + idx], u0);
        }
    }

    atomicAdd(&g_colSum[gq + 0], c0);
    atomicAdd(&g_colSum[gq + 1], c1);

    // --- last-block finalize (ticket) ---
    __syncthreads();
    if (tid == 0) {
        __threadfence();
        s_last = (atomicAdd(&g_done, 1u) == (unsigned)(NBLOCKS - 1)) ? 1u : 0u;
    }
    __syncthreads();
    if (s_last) {
        __threadfence();
        float s = 0.f;
        for (int p = tid; p < P2; p += 256)
            s += 30.0f + 0.5f * (logf(g_rowSum[p]) + logf(g_colSum[p])) - g_diag[p];
        s = warp_sum(s);
        if ((tid & 31) == 0) red[tid >> 5] = s;
        __syncthreads();
        if (tid == 0) {
            float tot = 0.f;
            #pragma unroll
            for (int k = 0; k < 8; ++k) tot += red[k];
            out[0] = tot / (float)P2;
        }
    }
}

extern "C" void kernel_launch(void* const* d_in, const int* in_sizes, int n_in,
                              void* d_out, int out_size) {
    const float* txtf = (const float*)d_in[0];
    const float* imgf = (const float*)d_in[1];
    (void)in_sizes; (void)n_in; (void)out_size;
    float* out = (float*)d_out;

    prep_kernel<<<NGRAMB + NMETAB, 256>>>(txtf, imgf);
    lse_main<<<dim3(GQ, GP), 256>>>(out);
}

// round 13
// speedup vs baseline: 1.1760x; 1.0036x over previous
#include <cuda_runtime.h>
#include <cstdint>

// DeltaLoss, rank-96 factorization. R13 = R12 with macro->template fix.
// Single-wave grid (864 blocks = 6 CTAs/SM, <= n_conc 888), block-uniform mask
// branch hoisted out of the loop.
//  prep : blocks 0..191 -> Gti rows; blocks 192..767 -> warp-per-pair meta + zeroing.
//  lse  : PBLK=384 x QBLK=64 tiles, 24KB W tile, lanes own a q-pair (LDS.64),
//         merged-butterfly row reduce, ticket finalize.
// SHIFT=30 fixed-shift LSE: x<=100 -> no overflow; sums stay normal fp32.

#define NN    96
#define D     512
#define P2    4560            // NN*(NN-1)/2
#define P2PAD 4608
#define PBLK  384
#define QBLK  64
#define GQ    (P2PAD / QBLK)  // 72
#define GP    (P2PAD / PBLK)  // 12
#define NBLOCKS (GQ * GP)     // 864
#define NGRAMB 192
#define NMETAB 576
#define K2C   (-43.28085122666891f)   // -30*log2(e)
#define L2E100 144.26950408889634f    // 100*log2(e)

// ---- scratch ----
__device__ float g_gti[NN * NN];
__device__ uint32_t g_ij[P2PAD];
__device__ float g_k1[P2PAD];
__device__ float g_si[P2PAD];
__device__ float g_diag[P2PAD];
__device__ float g_rowSum[P2PAD];
__device__ float g_colSum[P2PAD];
__device__ unsigned int g_done;

__device__ __forceinline__ float ex2f(float x) {
    float y;
    asm("ex2.approx.f32 %0, %1;" : "=f"(y) : "f"(x));
    return y;
}
__device__ __forceinline__ uint32_t smem_u32(const void* p) {
    uint32_t a;
    asm("{ .reg .u64 t; cvta.to.shared.u64 t, %1; cvt.u32.u64 %0, t; }" : "=r"(a) : "l"(p));
    return a;
}
__device__ __forceinline__ float warp_sum(float v) {
    #pragma unroll
    for (int o = 16; o > 0; o >>= 1) v += __shfl_xor_sync(0xffffffffu, v, o);
    return v;
}

// ---- prep: Gti (192 blocks) + per-pair meta & zeroing (576 blocks) ----
__global__ __launch_bounds__(256) void prep_kernel(const float* __restrict__ txtf,
                                                   const float* __restrict__ imgf) {
    __shared__ float srow[D];
    const int bid = blockIdx.x;
    const int tid = threadIdx.x;
    const int w = tid >> 5, lane = tid & 31;

    if (bid < NGRAMB) {
        const int b = bid >> 1, half = bid & 1;
        if (tid < 128) ((float4*)srow)[tid] = ((const float4*)(txtf + b * D))[tid];
        __syncthreads();
        #pragma unroll
        for (int k = 0; k < 6; ++k) {
            const int r = half * 48 + w * 6 + k;
            const float4* __restrict__ vec = (const float4*)(imgf + r * D);
            float s0 = 0.f, s1 = 0.f;
            #pragma unroll
            for (int e = 0; e < 4; e += 2) {
                const float4 a0 = ((const float4*)srow)[lane + e * 32];
                const float4 g0 = vec[lane + e * 32];
                const float4 a1 = ((const float4*)srow)[lane + (e + 1) * 32];
                const float4 g1 = vec[lane + (e + 1) * 32];
                s0 = fmaf(a0.x, g0.x, s0); s0 = fmaf(a0.y, g0.y, s0);
                s0 = fmaf(a0.z, g0.z, s0); s0 = fmaf(a0.w, g0.w, s0);
                s1 = fmaf(a1.x, g1.x, s1); s1 = fmaf(a1.y, g1.y, s1);
                s1 = fmaf(a1.z, g1.z, s1); s1 = fmaf(a1.w, g1.w, s1);
            }
            const float s = warp_sum(s0 + s1);
            if (lane == 0) g_gti[b * NN + r] = s;
        }
        return;
    }

    const int m = bid - NGRAMB;
    if (tid < 8)              g_rowSum[m * 8 + tid] = 0.f;
    else if (tid < 16)        g_colSum[m * 8 + tid - 8] = 0.f;
    else if (tid == 16 && m == 0) g_done = 0u;

    const int p = m * 8 + w;
    if (p >= P2) {
        if (p < P2PAD && lane == 0) {
            g_ij[p] = 0u; g_k1[p] = 0.f; g_si[p] = 0.f; g_diag[p] = 0.f;
        }
        return;
    }

    const float disc = (2.f * NN - 1.f) * (2.f * NN - 1.f) - 8.f * (float)p;
    int i = (int)(((2.f * NN - 1.f) - sqrtf(disc)) * 0.5f);
    i = i < 0 ? 0 : (i > NN - 2 ? NN - 2 : i);
    while (i > 0 && p < i * (191 - i) / 2) --i;
    while (p >= (i + 1) * (190 - i) / 2) ++i;
    const int j = i + 1 + (p - i * (191 - i) / 2);

    const float4* __restrict__ ti = (const float4*)(txtf + i * D);
    const float4* __restrict__ tj = (const float4*)(txtf + j * D);
    const float4* __restrict__ ui = (const float4*)(imgf + i * D);
    const float4* __restrict__ uj = (const float4*)(imgf + j * D);
    float ntt = 0.f, nii = 0.f, dd = 0.f;
    #pragma unroll
    for (int e = 0; e < 4; ++e) {
        const float4 a = ti[lane + e * 32], b4 = tj[lane + e * 32];
        const float4 c = ui[lane + e * 32], d4 = uj[lane + e * 32];
        const float t0 = a.x - b4.x, t1 = a.y - b4.y, t2 = a.z - b4.z, t3 = a.w - b4.w;
        const float u0 = c.x - d4.x, u1 = c.y - d4.y, u2 = c.z - d4.z, u3 = c.w - d4.w;
        ntt = fmaf(t0, t0, ntt); ntt = fmaf(t1, t1, ntt);
        ntt = fmaf(t2, t2, ntt); ntt = fmaf(t3, t3, ntt);
        nii = fmaf(u0, u0, nii); nii = fmaf(u1, u1, nii);
        nii = fmaf(u2, u2, nii); nii = fmaf(u3, u3, nii);
        dd  = fmaf(t0, u0, dd);  dd  = fmaf(t1, u1, dd);
        dd  = fmaf(t2, u2, dd);  dd  = fmaf(t3, u3, dd);
    }
    ntt = warp_sum(ntt); nii = warp_sum(nii); dd = warp_sum(dd);
    if (lane == 0) {
        const float st = 1.f / (sqrtf(ntt) + 1e-8f);
        const float si = 1.f / (sqrtf(nii) + 1e-8f);
        g_ij[p] = (uint32_t)i | ((uint32_t)j << 8);
        g_k1[p] = L2E100 * st;
        g_si[p] = si;
        g_diag[p] = 100.f * st * si * dd;
    }
}

// one group of 4 p: compute entries, butterfly-reduce rows, update col accumulators
template <bool MASKED>
__device__ __forceinline__ void lse_group(
    int g, int pbase, int p0, int lane, uint32_t wbase,
    const float2* __restrict__ ksm, const uint32_t* __restrict__ offsm,
    float mq0, float mq1, float& c0, float& c1)
{
    float rsv[4];
    #pragma unroll
    for (int u = 0; u < 4; ++u) {
        const int p = pbase + g * 4 + u;
        const uint32_t off = offsm[p];
        const float2 kb = ksm[p];
        float2 vi, vj;
        asm volatile("ld.shared.v2.f32 {%0,%1}, [%2];"
            : "=f"(vi.x), "=f"(vi.y) : "r"(wbase + (off & 0xFFFFu)));
        asm volatile("ld.shared.v2.f32 {%0,%1}, [%2];"
            : "=f"(vj.x), "=f"(vj.y) : "r"(wbase + (off >> 16)));
        const float d0 = vi.x - vj.x, d1 = vi.y - vj.y;
        const float e0 = ex2f(fmaf(d0, kb.x, kb.y)) + ex2f(fmaf(d0, -kb.x, kb.y));
        const float e1 = ex2f(fmaf(d1, kb.x, kb.y)) + ex2f(fmaf(d1, -kb.x, kb.y));
        c0 += e0; c1 += e1;
        if constexpr (MASKED) rsv[u] = fmaf(e1, mq1, e0 * mq0);
        else                  rsv[u] = e0 + e1;
    }
    // merged 4-way butterfly: lane-group (bit4, bit3) holds row sum of
    // p = pbase + g*4 + idx, idx = bit4 | (bit3 << 1)
    float v0 = rsv[0] + __shfl_xor_sync(0xffffffffu, rsv[0], 16);
    float t1 = rsv[1] + __shfl_xor_sync(0xffffffffu, rsv[1], 16);
    v0 = (lane & 16) ? t1 : v0;
    float v1 = rsv[2] + __shfl_xor_sync(0xffffffffu, rsv[2], 16);
    float t3 = rsv[3] + __shfl_xor_sync(0xffffffffu, rsv[3], 16);
    v1 = (lane & 16) ? t3 : v1;
    float u0 = v0 + __shfl_xor_sync(0xffffffffu, v0, 8);
    float u1 = v1 + __shfl_xor_sync(0xffffffffu, v1, 8);
    u0 = (lane & 8) ? u1 : u0;
    u0 += __shfl_xor_sync(0xffffffffu, u0, 4);
    u0 += __shfl_xor_sync(0xffffffffu, u0, 2);
    u0 += __shfl_xor_sync(0xffffffffu, u0, 1);
    if ((lane & 7) == 0) {
        const int idx = ((lane >> 4) & 1) | ((lane >> 2) & 2);
        atomicAdd(&g_rowSum[p0 + pbase + g * 4 + idx], u0);
    }
}

// ---- main: 24KB W tile, 384p x 64q per block, fused LSE, ticket finalize ----
__global__ void __launch_bounds__(256, 6) lse_main(float* __restrict__ out) {
    __shared__ float Wsm[NN * QBLK];                   // 24576 B
    __shared__ float2 ksm[PBLK];                       // (k1, base)
    __shared__ uint32_t offsm[PBLK];                   // packed byte offsets
    __shared__ float red[8];
    __shared__ unsigned int s_last;

    const int tid = threadIdx.x;
    const int q0 = blockIdx.x * QBLK;
    const int p0 = blockIdx.y * PBLK;

    // --- build W tile: Wsm[r][q] = si_q * (Gti[r][i_q] - Gti[r][j_q]) ---
    {
        const int q = tid & 63;
        const int rg = tid >> 6;                       // 4 groups of 24 rows
        const uint32_t ij = g_ij[q0 + q];
        const float si = g_si[q0 + q];
        const int iq = (int)(ij & 255u), jq = (int)(ij >> 8);
        const float* __restrict__ gi = g_gti + rg * 24 * NN;
        #pragma unroll 8
        for (int k = 0; k < 24; ++k) {
            const float a = __ldg(gi + k * NN + iq);
            const float b = __ldg(gi + k * NN + jq);
            Wsm[(rg * 24 + k) * QBLK + q] = si * (a - b);
        }
        // per-p metadata: 384 entries, 256 threads
        int p = p0 + tid;
        ksm[tid] = make_float2(g_k1[p], (p < P2) ? K2C : -2000.f);
        uint32_t pij = g_ij[p];
        offsm[tid] = ((pij & 255u) * (QBLK * 4)) | (((pij >> 8) * (QBLK * 4)) << 16);
        if (tid < PBLK - 256) {
            p = p0 + 256 + tid;
            ksm[256 + tid] = make_float2(g_k1[p], (p < P2) ? K2C : -2000.f);
            pij = g_ij[p];
            offsm[256 + tid] = ((pij & 255u) * (QBLK * 4))
                             | (((pij >> 8) * (QBLK * 4)) << 16);
        }
    }
    __syncthreads();

    const int w = tid >> 5, lane = tid & 31;
    const uint32_t wbase = smem_u32(Wsm) + (uint32_t)lane * 8u;
    const int pbase = w * 48;                          // 48 p per warp
    float c0 = 0.f, c1 = 0.f;
    const int gq = q0 + 2 * lane;

    if (q0 + QBLK <= P2) {
        #pragma unroll 2
        for (int g = 0; g < 12; ++g)
            lse_group<false>(g, pbase, p0, lane, wbase, ksm, offsm, 1.f, 1.f, c0, c1);
    } else {
        const float mq0 = (gq + 0 < P2) ? 1.f : 0.f;
        const float mq1 = (gq + 1 < P2) ? 1.f : 0.f;
        #pragma unroll 2
        for (int g = 0; g < 12; ++g)
            lse_group<true>(g, pbase, p0, lane, wbase, ksm, offsm, mq0, mq1, c0, c1);
    }

    atomicAdd(&g_colSum[gq + 0], c0);
    atomicAdd(&g_colSum[gq + 1], c1);

    // --- last-block finalize (ticket) ---
    __syncthreads();
    if (tid == 0) {
        __threadfence();
        s_last = (atomicAdd(&g_done, 1u) == (unsigned)(NBLOCKS - 1)) ? 1u : 0u;
    }
    __syncthreads();
    if (s_last) {
        __threadfence();
        float s = 0.f;
        for (int p = tid; p < P2; p += 256)
            s += 30.0f + 0.5f * (logf(g_rowSum[p]) + logf(g_colSum[p])) - g_diag[p];
        s = warp_sum(s);
        if ((tid & 31) == 0) red[tid >> 5] = s;
        __syncthreads();
        if (tid == 0) {
            float tot = 0.f;
            #pragma unroll
            for (int k = 0; k < 8; ++k) tot += red[k];
            out[0] = tot / (float)P2;
        }
    }
}

extern "C" void kernel_launch(void* const* d_in, const int* in_sizes, int n_in,
                              void* d_out, int out_size) {
    const float* txtf = (const float*)d_in[0];
    const float* imgf = (const float*)d_in[1];
    (void)in_sizes; (void)n_in; (void)out_size;
    float* out = (float*)d_out;

    prep_kernel<<<NGRAMB + NMETAB, 256>>>(txtf, imgf);
    lse_main<<<dim3(GQ, GP), 256>>>(out);
}

// round 14
// speedup vs baseline: 1.1803x; 1.0036x over previous
#include <cuda_runtime.h>
#include <cstdint>

// DeltaLoss, rank-96 factorization. R14: fix register spills (launch_bounds 256,5
// -> 48-reg budget) + PBLK=512 (grid 648, one wave at occ 5, -25% W-build work).
//  prep : blocks 0..191 -> Gti rows; blocks 192..767 -> warp-per-pair meta + zeroing.
//  lse  : PBLK=512 x QBLK=64 tiles, 24KB W tile, lanes own a q-pair (LDS.64),
//         merged-butterfly row reduce, ticket finalize.
// SHIFT=30 fixed-shift LSE: x<=100 -> no overflow; sums stay normal fp32.

#define NN    96
#define D     512
#define P2    4560            // NN*(NN-1)/2
#define P2PAD 4608
#define PBLK  512
#define QBLK  64
#define GQ    (P2PAD / QBLK)  // 72
#define GP    (P2PAD / PBLK)  // 9
#define NBLOCKS (GQ * GP)     // 648
#define NGRAMB 192
#define NMETAB 576
#define K2C   (-43.28085122666891f)   // -30*log2(e)
#define L2E100 144.26950408889634f    // 100*log2(e)

// ---- scratch ----
__device__ float g_gti[NN * NN];
__device__ uint32_t g_ij[P2PAD];
__device__ float g_k1[P2PAD];
__device__ float g_si[P2PAD];
__device__ float g_diag[P2PAD];
__device__ float g_rowSum[P2PAD];
__device__ float g_colSum[P2PAD];
__device__ unsigned int g_done;

__device__ __forceinline__ float ex2f(float x) {
    float y;
    asm("ex2.approx.f32 %0, %1;" : "=f"(y) : "f"(x));
    return y;
}
__device__ __forceinline__ uint32_t smem_u32(const void* p) {
    uint32_t a;
    asm("{ .reg .u64 t; cvta.to.shared.u64 t, %1; cvt.u32.u64 %0, t; }" : "=r"(a) : "l"(p));
    return a;
}
__device__ __forceinline__ float warp_sum(float v) {
    #pragma unroll
    for (int o = 16; o > 0; o >>= 1) v += __shfl_xor_sync(0xffffffffu, v, o);
    return v;
}

// ---- prep: Gti (192 blocks) + per-pair meta & zeroing (576 blocks) ----
__global__ __launch_bounds__(256) void prep_kernel(const float* __restrict__ txtf,
                                                   const float* __restrict__ imgf) {
    __shared__ float srow[D];
    const int bid = blockIdx.x;
    const int tid = threadIdx.x;
    const int w = tid >> 5, lane = tid & 31;

    if (bid < NGRAMB) {
        const int b = bid >> 1, half = bid & 1;
        if (tid < 128) ((float4*)srow)[tid] = ((const float4*)(txtf + b * D))[tid];
        __syncthreads();
        #pragma unroll
        for (int k = 0; k < 6; ++k) {
            const int r = half * 48 + w * 6 + k;
            const float4* __restrict__ vec = (const float4*)(imgf + r * D);
            float s0 = 0.f, s1 = 0.f;
            #pragma unroll
            for (int e = 0; e < 4; e += 2) {
                const float4 a0 = ((const float4*)srow)[lane + e * 32];
                const float4 g0 = vec[lane + e * 32];
                const float4 a1 = ((const float4*)srow)[lane + (e + 1) * 32];
                const float4 g1 = vec[lane + (e + 1) * 32];
                s0 = fmaf(a0.x, g0.x, s0); s0 = fmaf(a0.y, g0.y, s0);
                s0 = fmaf(a0.z, g0.z, s0); s0 = fmaf(a0.w, g0.w, s0);
                s1 = fmaf(a1.x, g1.x, s1); s1 = fmaf(a1.y, g1.y, s1);
                s1 = fmaf(a1.z, g1.z, s1); s1 = fmaf(a1.w, g1.w, s1);
            }
            const float s = warp_sum(s0 + s1);
            if (lane == 0) g_gti[b * NN + r] = s;
        }
        return;
    }

    const int m = bid - NGRAMB;
    if (tid < 8)              g_rowSum[m * 8 + tid] = 0.f;
    else if (tid < 16)        g_colSum[m * 8 + tid - 8] = 0.f;
    else if (tid == 16 && m == 0) g_done = 0u;

    const int p = m * 8 + w;
    if (p >= P2) {
        if (p < P2PAD && lane == 0) {
            g_ij[p] = 0u; g_k1[p] = 0.f; g_si[p] = 0.f; g_diag[p] = 0.f;
        }
        return;
    }

    const float disc = (2.f * NN - 1.f) * (2.f * NN - 1.f) - 8.f * (float)p;
    int i = (int)(((2.f * NN - 1.f) - sqrtf(disc)) * 0.5f);
    i = i < 0 ? 0 : (i > NN - 2 ? NN - 2 : i);
    while (i > 0 && p < i * (191 - i) / 2) --i;
    while (p >= (i + 1) * (190 - i) / 2) ++i;
    const int j = i + 1 + (p - i * (191 - i) / 2);

    const float4* __restrict__ ti = (const float4*)(txtf + i * D);
    const float4* __restrict__ tj = (const float4*)(txtf + j * D);
    const float4* __restrict__ ui = (const float4*)(imgf + i * D);
    const float4* __restrict__ uj = (const float4*)(imgf + j * D);
    float ntt = 0.f, nii = 0.f, dd = 0.f;
    #pragma unroll
    for (int e = 0; e < 4; ++e) {
        const float4 a = ti[lane + e * 32], b4 = tj[lane + e * 32];
        const float4 c = ui[lane + e * 32], d4 = uj[lane + e * 32];
        const float t0 = a.x - b4.x, t1 = a.y - b4.y, t2 = a.z - b4.z, t3 = a.w - b4.w;
        const float u0 = c.x - d4.x, u1 = c.y - d4.y, u2 = c.z - d4.z, u3 = c.w - d4.w;
        ntt = fmaf(t0, t0, ntt); ntt = fmaf(t1, t1, ntt);
        ntt = fmaf(t2, t2, ntt); ntt = fmaf(t3, t3, ntt);
        nii = fmaf(u0, u0, nii); nii = fmaf(u1, u1, nii);
        nii = fmaf(u2, u2, nii); nii = fmaf(u3, u3, nii);
        dd  = fmaf(t0, u0, dd);  dd  = fmaf(t1, u1, dd);
        dd  = fmaf(t2, u2, dd);  dd  = fmaf(t3, u3, dd);
    }
    ntt = warp_sum(ntt); nii = warp_sum(nii); dd = warp_sum(dd);
    if (lane == 0) {
        const float st = 1.f / (sqrtf(ntt) + 1e-8f);
        const float si = 1.f / (sqrtf(nii) + 1e-8f);
        g_ij[p] = (uint32_t)i | ((uint32_t)j << 8);
        g_k1[p] = L2E100 * st;
        g_si[p] = si;
        g_diag[p] = 100.f * st * si * dd;
    }
}

// one group of 4 p: compute entries, butterfly-reduce rows, update col accumulators
template <bool MASKED>
__device__ __forceinline__ void lse_group(
    int g, int pbase, int p0, int lane, uint32_t wbase,
    const float2* __restrict__ ksm, const uint32_t* __restrict__ offsm,
    float mq0, float mq1, float& c0, float& c1)
{
    float rsv[4];
    #pragma unroll
    for (int u = 0; u < 4; ++u) {
        const int p = pbase + g * 4 + u;
        const uint32_t off = offsm[p];
        const float2 kb = ksm[p];
        float2 vi, vj;
        asm volatile("ld.shared.v2.f32 {%0,%1}, [%2];"
            : "=f"(vi.x), "=f"(vi.y) : "r"(wbase + (off & 0xFFFFu)));
        asm volatile("ld.shared.v2.f32 {%0,%1}, [%2];"
            : "=f"(vj.x), "=f"(vj.y) : "r"(wbase + (off >> 16)));
        const float d0 = vi.x - vj.x, d1 = vi.y - vj.y;
        const float e0 = ex2f(fmaf(d0, kb.x, kb.y)) + ex2f(fmaf(d0, -kb.x, kb.y));
        const float e1 = ex2f(fmaf(d1, kb.x, kb.y)) + ex2f(fmaf(d1, -kb.x, kb.y));
        c0 += e0; c1 += e1;
        if constexpr (MASKED) rsv[u] = fmaf(e1, mq1, e0 * mq0);
        else                  rsv[u] = e0 + e1;
    }
    // merged 4-way butterfly: lane-group (bit4, bit3) holds row sum of
    // p = pbase + g*4 + idx, idx = bit4 | (bit3 << 1)
    float v0 = rsv[0] + __shfl_xor_sync(0xffffffffu, rsv[0], 16);
    float t1 = rsv[1] + __shfl_xor_sync(0xffffffffu, rsv[1], 16);
    v0 = (lane & 16) ? t1 : v0;
    float v1 = rsv[2] + __shfl_xor_sync(0xffffffffu, rsv[2], 16);
    float t3 = rsv[3] + __shfl_xor_sync(0xffffffffu, rsv[3], 16);
    v1 = (lane & 16) ? t3 : v1;
    float u0 = v0 + __shfl_xor_sync(0xffffffffu, v0, 8);
    float u1 = v1 + __shfl_xor_sync(0xffffffffu, v1, 8);
    u0 = (lane & 8) ? u1 : u0;
    u0 += __shfl_xor_sync(0xffffffffu, u0, 4);
    u0 += __shfl_xor_sync(0xffffffffu, u0, 2);
    u0 += __shfl_xor_sync(0xffffffffu, u0, 1);
    if ((lane & 7) == 0) {
        const int idx = ((lane >> 4) & 1) | ((lane >> 2) & 2);
        atomicAdd(&g_rowSum[p0 + pbase + g * 4 + idx], u0);
    }
}

// ---- main: 24KB W tile, 512p x 64q per block, fused LSE, ticket finalize ----
__global__ void __launch_bounds__(256, 5) lse_main(float* __restrict__ out) {
    __shared__ float Wsm[NN * QBLK];                   // 24576 B
    __shared__ float2 ksm[PBLK];                       // (k1, base)
    __shared__ uint32_t offsm[PBLK];                   // packed byte offsets
    __shared__ float red[8];
    __shared__ unsigned int s_last;

    const int tid = threadIdx.x;
    const int q0 = blockIdx.x * QBLK;
    const int p0 = blockIdx.y * PBLK;

    // --- build W tile: Wsm[r][q] = si_q * (Gti[r][i_q] - Gti[r][j_q]) ---
    {
        const int q = tid & 63;
        const int rg = tid >> 6;                       // 4 groups of 24 rows
        const uint32_t ij = g_ij[q0 + q];
        const float si = g_si[q0 + q];
        const int iq = (int)(ij & 255u), jq = (int)(ij >> 8);
        const float* __restrict__ gi = g_gti + rg * 24 * NN;
        #pragma unroll 8
        for (int k = 0; k < 24; ++k) {
            const float a = __ldg(gi + k * NN + iq);
            const float b = __ldg(gi + k * NN + jq);
            Wsm[(rg * 24 + k) * QBLK + q] = si * (a - b);
        }
        // per-p metadata: 512 entries, 256 threads
        #pragma unroll
        for (int r = 0; r < 2; ++r) {
            const int pi = tid + r * 256;
            const int p = p0 + pi;
            ksm[pi] = make_float2(g_k1[p], (p < P2) ? K2C : -2000.f);
            const uint32_t pij = g_ij[p];
            offsm[pi] = ((pij & 255u) * (QBLK * 4)) | (((pij >> 8) * (QBLK * 4)) << 16);
        }
    }
    __syncthreads();

    const int w = tid >> 5, lane = tid & 31;
    const uint32_t wbase = smem_u32(Wsm) + (uint32_t)lane * 8u;
    const int pbase = w * 64;                          // 64 p per warp
    float c0 = 0.f, c1 = 0.f;
    const int gq = q0 + 2 * lane;

    if (q0 + QBLK <= P2) {
        #pragma unroll 2
        for (int g = 0; g < 16; ++g)
            lse_group<false>(g, pbase, p0, lane, wbase, ksm, offsm, 1.f, 1.f, c0, c1);
    } else {
        const float mq0 = (gq + 0 < P2) ? 1.f : 0.f;
        const float mq1 = (gq + 1 < P2) ? 1.f : 0.f;
        #pragma unroll 2
        for (int g = 0; g < 16; ++g)
            lse_group<true>(g, pbase, p0, lane, wbase, ksm, offsm, mq0, mq1, c0, c1);
    }

    atomicAdd(&g_colSum[gq + 0], c0);
    atomicAdd(&g_colSum[gq + 1], c1);

    // --- last-block finalize (ticket) ---
    __syncthreads();
    if (tid == 0) {
        __threadfence();
        s_last = (atomicAdd(&g_done, 1u) == (unsigned)(NBLOCKS - 1)) ? 1u : 0u;
    }
    __syncthreads();
    if (s_last) {
        __threadfence();
        float s = 0.f;
        for (int p = tid; p < P2; p += 256)
            s += 30.0f + 0.5f * (logf(g_rowSum[p]) + logf(g_colSum[p])) - g_diag[p];
        s = warp_sum(s);
        if ((tid & 31) == 0) red[tid >> 5] = s;
        __syncthreads();
        if (tid == 0) {
            float tot = 0.f;
            #pragma unroll
            for (int k = 0; k < 8; ++k) tot += red[k];
            out[0] = tot / (float)P2;
        }
    }
}

extern "C" void kernel_launch(void* const* d_in, const int* in_sizes, int n_in,
                              void* d_out, int out_size) {
    const float* txtf = (const float*)d_in[0];
    const float* imgf = (const float*)d_in[1];
    (void)in_sizes; (void)n_in; (void)out_size;
    float* out = (float*)d_out;

    prep_kernel<<<NGRAMB + NMETAB, 256>>>(txtf, imgf);
    lse_main<<<dim3(GQ, GP), 256>>>(out);
}